// round 1
// baseline (speedup 1.0000x reference)
#include <cuda_runtime.h>
#include <cuda_bf16.h>
#include <math.h>

// Problem constants
#define Bb 4
#define Tt 2048
#define Dd 2048
#define Hh 16
#define Gg 4
#define Kk 128
#define Rr 4          // H / G
#define EPS 1e-6f
#define ROPE_BASE 10000.0f
#define SOFTMAX_SCALE 0.08838834764831845f  // K^-0.5

#define MTOT (Bb * Tt)          // 8192 rows

// --------------------------- scratch (device globals; no mallocs) ------------
__device__ float g_q[(size_t)MTOT * Hh * Kk];     // 64 MB
__device__ float g_k[(size_t)MTOT * Gg * Kk];     // 16 MB
__device__ float g_v[(size_t)MTOT * Gg * Kk];     // 16 MB
__device__ float g_attn[(size_t)MTOT * Hh * Kk];  // 64 MB
__device__ int   g_pos[MTOT];

// --------------------------- SGEMM: C[M,N] = A[M,Kd] @ B[Kd,N] ---------------
// 128x128 tile, BK=8, 256 threads, 8x8 per thread, fp32 FMA.
// Requires M%128==0, N%128==0, Kd%8==0 (true for all our shapes).
#define BM 128
#define BN 128
#define BK 8
#define TM 8
#define TN 8

__global__ __launch_bounds__(256, 2)
void sgemm_kernel(int M, int N, int Kd,
                  const float* __restrict__ A,
                  const float* __restrict__ B,
                  float* __restrict__ C) {
    __shared__ float As[BK][BM];
    __shared__ float Bs[BK][BN];

    const int tid  = threadIdx.x;
    const int cRow = blockIdx.y;
    const int cCol = blockIdx.x;

    A += (size_t)cRow * BM * Kd;
    B += (size_t)cCol * BN;
    C += (size_t)cRow * BM * N + (size_t)cCol * BN;

    // A tile load: 128 rows x 8 cols = 1024 floats; one float4 per thread
    const int aRow = tid >> 1;           // 0..127
    const int aCol = (tid & 1) * 4;      // 0 or 4
    // B tile load: 8 rows x 128 cols; one float4 per thread
    const int bRow = tid >> 5;           // 0..7
    const int bCol = (tid & 31) * 4;     // 0..124

    const int ty = (tid / 16) * TM;
    const int tx = (tid % 16) * TN;

    float acc[TM][TN];
#pragma unroll
    for (int i = 0; i < TM; i++)
#pragma unroll
        for (int j = 0; j < TN; j++) acc[i][j] = 0.f;

    float rA[TM], rB[TN];

    for (int k0 = 0; k0 < Kd; k0 += BK) {
        float4 a4 = *(const float4*)(A + (size_t)aRow * Kd + k0 + aCol);
        As[aCol + 0][aRow] = a4.x;
        As[aCol + 1][aRow] = a4.y;
        As[aCol + 2][aRow] = a4.z;
        As[aCol + 3][aRow] = a4.w;
        float4 b4 = *(const float4*)(B + (size_t)(k0 + bRow) * N + bCol);
        *(float4*)&Bs[bRow][bCol] = b4;
        __syncthreads();

#pragma unroll
        for (int kk = 0; kk < BK; kk++) {
#pragma unroll
            for (int i = 0; i < TM; i++) rA[i] = As[kk][ty + i];
#pragma unroll
            for (int j = 0; j < TN; j++) rB[j] = Bs[kk][tx + j];
#pragma unroll
            for (int i = 0; i < TM; i++)
#pragma unroll
                for (int j = 0; j < TN; j++)
                    acc[i][j] = fmaf(rA[i], rB[j], acc[i][j]);
        }
        __syncthreads();
    }

#pragma unroll
    for (int i = 0; i < TM; i++)
#pragma unroll
        for (int j = 0; j < TN; j += 4) {
            float4 o = make_float4(acc[i][j], acc[i][j + 1], acc[i][j + 2], acc[i][j + 3]);
            *(float4*)(C + (size_t)(ty + i) * N + tx + j) = o;
        }
}

// --------------------------- positions from sorted segment ids ---------------
__global__ void pos_kernel(const int* __restrict__ seg, int* __restrict__ pos) {
    int idx = blockIdx.x * blockDim.x + threadIdx.x;
    if (idx >= MTOT) return;
    int b = idx / Tt;
    int t = idx % Tt;
    const int* row = seg + (size_t)b * Tt;
    int s = row[t];
    // lower_bound on sorted row -> first index of this segment value
    int lo = 0, hi = t;
    while (lo < hi) {
        int mid = (lo + hi) >> 1;
        if (row[mid] < s) lo = mid + 1; else hi = mid;
    }
    pos[idx] = t - lo;
}

// --------------------------- fused RMSNorm + RoPE (in place) -----------------
// One 128-thread block per head vector. NH = H for q, G for k.
__global__ __launch_bounds__(128)
void rms_rope_kernel(float* __restrict__ x, const float* __restrict__ scale,
                     const int* __restrict__ pos, int NH) {
    const int bt = blockIdx.x / NH;
    const int h  = blockIdx.x % NH;
    float* p = x + ((size_t)bt * NH + h) * Kk;

    const int i = threadIdx.x;
    float v = p[i];

    __shared__ float red[4];
    __shared__ float sx[Kk];
    float sq = v * v;
#pragma unroll
    for (int o = 16; o; o >>= 1) sq += __shfl_xor_sync(0xffffffffu, sq, o);
    if ((i & 31) == 0) red[i >> 5] = sq;
    __syncthreads();
    float var = (red[0] + red[1] + red[2] + red[3]) * (1.0f / Kk);
    float xn  = v * rsqrtf(var + EPS) * scale[i];
    sx[i] = xn;
    __syncthreads();

    if (i < Kk / 2) {
        float x1 = sx[i];
        float x2 = sx[i + Kk / 2];
        float pp = (float)pos[bt];
        // inv_freq = exp(-ln(base) * 2i/K)
        float inv = expf(-logf(ROPE_BASE) * (2.0f * (float)i / (float)Kk));
        float ang = pp * inv;
        float s, c;
        sincosf(ang, &s, &c);
        p[i]           = x1 * c - x2 * s;
        p[i + Kk / 2]  = x2 * c + x1 * s;
    }
}

// --------------------------- attention: warp per (b,t,h) ---------------------
// Key window is contiguous: s in [t - pos[t], t] (causal AND same-segment,
// because segment_ids are sorted => segments are contiguous runs).
__global__ __launch_bounds__(256)
void attn_kernel(const float* __restrict__ q, const float* __restrict__ k,
                 const float* __restrict__ v, const int* __restrict__ pos,
                 float* __restrict__ out) {
    const int warp = threadIdx.x >> 5;
    const int lane = threadIdx.x & 31;
    const long gw = (long)blockIdx.x * 8 + warp;   // global warp id
    // gw in [0, B*T*H)
    const int b = (int)(gw / ((long)Tt * Hh));
    const int rem = (int)(gw % ((long)Tt * Hh));
    const int t = rem / Hh;
    const int h = rem % Hh;
    const int g = h / Rr;

    const float* qp = q + (((size_t)b * Tt + t) * Hh + h) * Kk;
    float q0 = qp[lane];
    float q1 = qp[lane + 32];
    float q2 = qp[lane + 64];
    float q3 = qp[lane + 96];

    const int p  = pos[b * Tt + t];
    const int s0 = t - p;

    float m = -INFINITY, l = 0.f;
    float a0 = 0.f, a1 = 0.f, a2 = 0.f, a3 = 0.f;

    const float* kbase = k + ((size_t)b * Tt * Gg + g) * Kk;
    const float* vbase = v + ((size_t)b * Tt * Gg + g) * Kk;

    for (int s = s0; s <= t; ++s) {
        const float* kp = kbase + (size_t)s * Gg * Kk;
        float sc = q0 * kp[lane] + q1 * kp[lane + 32]
                 + q2 * kp[lane + 64] + q3 * kp[lane + 96];
#pragma unroll
        for (int o = 16; o; o >>= 1) sc += __shfl_xor_sync(0xffffffffu, sc, o);
        sc *= SOFTMAX_SCALE;

        float mn   = fmaxf(m, sc);
        float corr = __expf(m - mn);      // 0 on first iter (m = -inf)
        float pe   = __expf(sc - mn);
        l = l * corr + pe;

        const float* vp = vbase + (size_t)s * Gg * Kk;
        a0 = a0 * corr + pe * vp[lane];
        a1 = a1 * corr + pe * vp[lane + 32];
        a2 = a2 * corr + pe * vp[lane + 64];
        a3 = a3 * corr + pe * vp[lane + 96];
        m = mn;
    }

    float inv = 1.0f / l;
    float* op = out + (((size_t)b * Tt + t) * Hh + h) * Kk;
    op[lane]      = a0 * inv;
    op[lane + 32] = a1 * inv;
    op[lane + 64] = a2 * inv;
    op[lane + 96] = a3 * inv;
}

// --------------------------- launch --------------------------------------
extern "C" void kernel_launch(void* const* d_in, const int* in_sizes, int n_in,
                              void* d_out, int out_size) {
    const float* hidden = (const float*)d_in[0];
    const float* wq     = (const float*)d_in[1];
    const float* wk     = (const float*)d_in[2];
    const float* wv     = (const float*)d_in[3];
    const float* wo     = (const float*)d_in[4];
    const float* q_scale = (const float*)d_in[5];
    const float* k_scale = (const float*)d_in[6];
    const int*   seg    = (const int*)d_in[7];
    float* out = (float*)d_out;

    float *qb, *kb, *vb, *ab;
    int* posb;
    cudaGetSymbolAddress((void**)&qb, g_q);
    cudaGetSymbolAddress((void**)&kb, g_k);
    cudaGetSymbolAddress((void**)&vb, g_v);
    cudaGetSymbolAddress((void**)&ab, g_attn);
    cudaGetSymbolAddress((void**)&posb, g_pos);

    // 1) QKV projections
    {
        dim3 blk(256);
        dim3 grdQ((Hh * Kk) / BN, MTOT / BM);
        sgemm_kernel<<<grdQ, blk>>>(MTOT, Hh * Kk, Dd, hidden, wq, qb);
        dim3 grdK((Gg * Kk) / BN, MTOT / BM);
        sgemm_kernel<<<grdK, blk>>>(MTOT, Gg * Kk, Dd, hidden, wk, kb);
        sgemm_kernel<<<grdK, blk>>>(MTOT, Gg * Kk, Dd, hidden, wv, vb);
    }

    // 2) positions
    pos_kernel<<<(MTOT + 255) / 256, 256>>>(seg, posb);

    // 3) RMSNorm + RoPE (in place) on q and k
    rms_rope_kernel<<<MTOT * Hh, 128>>>(qb, q_scale, posb, Hh);
    rms_rope_kernel<<<MTOT * Gg, 128>>>(kb, k_scale, posb, Gg);

    // 4) attention: one warp per (b,t,h)
    {
        long total_warps = (long)MTOT * Hh;          // 131072
        int blocks = (int)(total_warps / 8);
        attn_kernel<<<blocks, 256>>>(qb, kb, vb, posb, ab);
    }

    // 5) output projection
    {
        dim3 blk(256);
        dim3 grd(Dd / BN, MTOT / BM);
        sgemm_kernel<<<grd, blk>>>(MTOT, Dd, Hh * Kk, ab, wo, out);
    }
}